// round 16
// baseline (speedup 1.0000x reference)
#include <cuda_runtime.h>
#include <math.h>
#include <stdint.h>

#define BATCH 16
#define LQ 128
#define LP 512
#define H 32
#define DH 32
#define SST 68                     /* padded row stride for s tile */
#define SCALE 0.17677669529663687f /* 32^-0.5 */

// ---------------- scratch (static device arrays; no allocs) ----------------
__device__ float g_QK[2048 * 1024];        // [n][h*32+d]
__device__ float g_CQKt[16 * 1024 * 512];  // [b][c][j]  (transposed)
__device__ float g_CV[8192 * 1024];        // [b*512+j][h*32+d]
__device__ float g_S[16 * 8 * 512 * 16 * 64];    // [b][it][j][ih][il8][ch64] : p
__device__ float g_smax[16 * 8 * 16 * 16 * 64];  // [b][it][chunk][il][ch]
__device__ float g_ssum[16 * 8 * 16 * 16 * 64];
__device__ float g_pAV[16 * 8 * 4 * 16 * 1024];  // [b][it][js][il][c]
__device__ float g_pD[16 * 8 * 4 * 1536];        // [b][it][js][job]

// fast mish: x * (t^2-1)/(t^2+1), t = 1+e^x
__device__ __forceinline__ float mishf(float x) {
    if (x > 20.f) return x;
    float t = 1.f + __expf(x);
    float t2 = t * t;
    return x * __fdividef(t2 - 1.f, t2 + 1.f);
}

__device__ __forceinline__ uint32_t tf32_cvt(float x) {
    uint32_t r;
    asm("cvt.rna.tf32.f32 %0, %1;" : "=r"(r) : "f"(x));
    return r;
}

__device__ __forceinline__ void mma_tf32(float* d, uint32_t a0, uint32_t a1,
                                         uint32_t a2, uint32_t a3, uint32_t b0,
                                         uint32_t b1) {
    asm volatile(
        "mma.sync.aligned.m16n8k8.row.col.f32.tf32.tf32.f32 "
        "{%0,%1,%2,%3}, {%4,%5,%6,%7}, {%8,%9}, {%0,%1,%2,%3};\n"
        : "+f"(d[0]), "+f"(d[1]), "+f"(d[2]), "+f"(d[3])
        : "r"(a0), "r"(a1), "r"(a2), "r"(a3), "r"(b0), "r"(b1));
}

// ---------------- fused projection GEMM (tf32 mma) --------------------------
#define PROJ_SMEM_FLOATS 8448
#define PROJ_SMEM_BYTES (PROJ_SMEM_FLOATS * 4)

__global__ __launch_bounds__(256) void proj_fused(
    const float* __restrict__ x, const float* __restrict__ ctx,
    const float* __restrict__ W_qk, const float* __restrict__ W_cqk,
    const float* __restrict__ W_cv) {
    int mode = blockIdx.z;
    if (mode == 0 && blockIdx.x >= 32) return;

    extern __shared__ float smp[];
    float* sA = smp;              // [64][36]
    float* sW = smp + 64 * 36;    // [32][132]
    float* sC = smp;              // [64][132] alias (mode-1 epilogue)

    const float* A = (mode == 0) ? x : ctx;
    const float* W = (mode == 0) ? W_qk : (mode == 1 ? W_cqk : W_cv);
    float* outp = (mode == 0) ? g_QK : (mode == 1 ? g_CQKt : g_CV);

    int t = threadIdx.x, lane = t & 31, w = t >> 5;
    int m0 = blockIdx.x * 64, n0 = blockIdx.y * 128;
    int wm = w >> 1, wn = w & 1;
    int g = lane >> 2, tig = lane & 3;

    float acc[8][4];
#pragma unroll
    for (int nt = 0; nt < 8; nt++)
#pragma unroll
        for (int q = 0; q < 4; q++) acc[nt][q] = 0.f;

    for (int k0 = 0; k0 < 256; k0 += 32) {
#pragma unroll
        for (int f = 0; f < 2; f++) {
            int job = t + 256 * f;
            int r = job >> 3, c4 = job & 7;
            float4 v = reinterpret_cast<const float4*>(A)[(size_t)(m0 + r) * 64 + (k0 >> 2) + c4];
            *reinterpret_cast<float4*>(&sA[r * 36 + c4 * 4]) = v;
        }
#pragma unroll
        for (int f = 0; f < 4; f++) {
            int job = t + 256 * f;
            int kk = job >> 5, c4 = job & 31;
            float4 v = reinterpret_cast<const float4*>(W)[(size_t)(k0 + kk) * 256 + (n0 >> 2) + c4];
            *reinterpret_cast<float4*>(&sW[kk * 132 + c4 * 4]) = v;
        }
        __syncthreads();
#pragma unroll
        for (int k8 = 0; k8 < 4; k8++) {
            const float* ap = sA + (wm * 16 + g) * 36 + k8 * 8 + tig;
            uint32_t a0 = tf32_cvt(ap[0]);
            uint32_t a1 = tf32_cvt(ap[8 * 36]);
            uint32_t a2 = tf32_cvt(ap[4]);
            uint32_t a3 = tf32_cvt(ap[8 * 36 + 4]);
#pragma unroll
            for (int nt = 0; nt < 8; nt++) {
                const float* bp = sW + (k8 * 8 + tig) * 132 + wn * 64 + nt * 8 + g;
                uint32_t b0 = tf32_cvt(bp[0]);
                uint32_t b1 = tf32_cvt(bp[4 * 132]);
                mma_tf32(acc[nt], a0, a1, a2, a3, b0, b1);
            }
        }
        __syncthreads();
    }

    if (mode != 1) {
#pragma unroll
        for (int nt = 0; nt < 8; nt++) {
            int col = n0 + wn * 64 + nt * 8 + 2 * tig;
            int row = m0 + wm * 16 + g;
            *reinterpret_cast<float2*>(&outp[(size_t)row * 1024 + col]) =
                make_float2(acc[nt][0], acc[nt][1]);
            *reinterpret_cast<float2*>(&outp[(size_t)(row + 8) * 1024 + col]) =
                make_float2(acc[nt][2], acc[nt][3]);
        }
    } else {
#pragma unroll
        for (int nt = 0; nt < 8; nt++) {
            int col = wn * 64 + nt * 8 + 2 * tig;
            int row = wm * 16 + g;
            *reinterpret_cast<float2*>(&sC[row * 132 + col]) =
                make_float2(acc[nt][0], acc[nt][1]);
            *reinterpret_cast<float2*>(&sC[(row + 8) * 132 + col]) =
                make_float2(acc[nt][2], acc[nt][3]);
        }
        __syncthreads();
        int bb = m0 >> 9, jbase = m0 & 511;
#pragma unroll
        for (int f = 0; f < 32; f++) {
            int job = t + 256 * f;
            int cc = job >> 6, jj = job & 63;
            outp[((size_t)bb * 1024 + n0 + cc) * 512 + jbase + jj] = sC[jj * 132 + cc];
        }
    }
}

// ---------------- K1: score kernel -----------------------------------------
#define OFF1_W1F 34816
#define OFF1_W2F 43008
#define OFF1_BM2 51200
#define OFF1_STG 51264
#define K1_FLOATS 53824
#define K1_BYTES (K1_FLOATS * 4)

__global__ __launch_bounds__(512, 1) void score_kernel(
    const float* __restrict__ dis_emb, const float* __restrict__ W_m1,
    const float* __restrict__ W_m2, const float* __restrict__ b_m2) {
    extern __shared__ float sm[];
    float* cqks = sm;  // [1024][33]
    float* sS = sm;    // [512][68] after sim
    float2* w1f = reinterpret_cast<float2*>(sm + OFF1_W1F);
    float2* w2f = reinterpret_cast<float2*>(sm + OFF1_W2F);

    int t = threadIdx.x, lane = t & 31, w = t >> 5;
    int chunk = blockIdx.x, it = blockIdx.y, b = blockIdx.z;
    int j0 = chunk * 32, i0 = it * 16;
    int g = lane >> 2, tig = lane & 3;
    int cb = b * 8 + it;

    // stage CQK chunk [1024][33]
    {
        const float* src = g_CQKt + (size_t)b * 1024 * 512 + j0;
        for (int k = 0; k < 64; k++) {
            int fl = t + 512 * k;
            int c = fl >> 5, jj = fl & 31;
            cqks[c * 33 + jj] = src[(size_t)c * 512 + jj];
        }
    }
    // weight fragments (tf32 pre-rounded)
#pragma unroll
    for (int p = 0; p < 8; p++) {
        int idx = t + 512 * p;
        int fi = idx >> 5, ln = idx & 31;
        int gg = ln >> 2, tt = ln & 3;
        {
            int k8 = fi >> 4, nt = fi & 15;
            float b0 = W_m1[(k8 * 8 + tt) * 128 + nt * 8 + gg];
            float b1 = W_m1[(k8 * 8 + tt + 4) * 128 + nt * 8 + gg];
            w1f[idx] = make_float2(__uint_as_float(tf32_cvt(b0)),
                                   __uint_as_float(tf32_cvt(b1)));
        }
        {
            int kt = fi >> 3, n2 = fi & 7;
            float c0 = W_m2[(kt * 8 + tt) * 64 + n2 * 8 + gg];
            float c1 = W_m2[(kt * 8 + tt + 4) * 64 + n2 * 8 + gg];
            w2f[idx] = make_float2(__uint_as_float(tf32_cvt(c0)),
                                   __uint_as_float(tf32_cvt(c1)));
        }
    }
    if (t < 64) sm[OFF1_BM2 + t] = b_m2[t];
    __syncthreads();

    // ---- sim via mma.sync tf32: per head D[32j,16i] = CQK @ QK^T ----
    float Dh[2][2][2][4];
    {
        const float* qkb = g_QK + (size_t)(b * 128 + i0) * 1024;
#pragma unroll
        for (int hh = 0; hh < 2; hh++) {
            int h = w * 2 + hh;
#pragma unroll
            for (int mt = 0; mt < 2; mt++)
#pragma unroll
                for (int nt = 0; nt < 2; nt++)
#pragma unroll
                    for (int q = 0; q < 4; q++) Dh[hh][mt][nt][q] = 0.f;
#pragma unroll
            for (int kt = 0; kt < 4; kt++) {
                const float* ap = cqks + (h * 32 + kt * 8 + tig) * 33 + g;
                uint32_t a00 = tf32_cvt(ap[0]);
                uint32_t a01 = tf32_cvt(ap[8]);
                uint32_t a02 = tf32_cvt(ap[4 * 33]);
                uint32_t a03 = tf32_cvt(ap[4 * 33 + 8]);
                uint32_t a10 = tf32_cvt(ap[16]);
                uint32_t a11 = tf32_cvt(ap[24]);
                uint32_t a12 = tf32_cvt(ap[4 * 33 + 16]);
                uint32_t a13 = tf32_cvt(ap[4 * 33 + 24]);
#pragma unroll
                for (int nt = 0; nt < 2; nt++) {
                    const float* bp = qkb + (size_t)(nt * 8 + g) * 1024 + h * 32 + kt * 8 + tig;
                    uint32_t b0 = tf32_cvt(__ldg(bp));
                    uint32_t b1 = tf32_cvt(__ldg(bp + 4));
                    mma_tf32(Dh[hh][0][nt], a00, a01, a02, a03, b0, b1);
                    mma_tf32(Dh[hh][1][nt], a10, a11, a12, a13, b0, b1);
                }
            }
        }
    }
    __syncthreads();  // all cqks reads done; region becomes sS

    // scatter sim into sS; load dis_emb channels
    {
#pragma unroll
        for (int hh = 0; hh < 2; hh++) {
            int h = w * 2 + hh;
#pragma unroll
            for (int mt = 0; mt < 2; mt++)
#pragma unroll
                for (int nt = 0; nt < 2; nt++) {
                    int jr = mt * 16 + g;
                    int ic = nt * 8 + 2 * tig;
                    sS[(ic * 32 + jr) * SST + h] = Dh[hh][mt][nt][0] * SCALE;
                    sS[((ic + 1) * 32 + jr) * SST + h] = Dh[hh][mt][nt][1] * SCALE;
                    sS[(ic * 32 + jr + 8) * SST + h] = Dh[hh][mt][nt][2] * SCALE;
                    sS[((ic + 1) * 32 + jr + 8) * SST + h] = Dh[hh][mt][nt][3] * SCALE;
                }
        }
        const float4* de4 = reinterpret_cast<const float4*>(dis_emb);
        for (int k = 0; k < 8; k++) {
            int fl = t + 512 * k;
            int jj = fl >> 7, r = fl & 127, il = r >> 3, h4 = r & 7;
            float4 v = de4[((size_t)(b * 512 + j0 + jj) * 128 + i0 + il) * 8 + h4];
            *reinterpret_cast<float4*>(&sS[(il * 32 + jj) * SST + 32 + h4 * 4]) = v;
        }
    }
    __syncthreads();

    // ---- MLP via mma.sync tf32 (A-frags hoisted, smem staging remap) ----
    {
        int j0w = w * 32;
        float* stg = sm + OFF1_STG + w * 160;  // 16 rows x stride 10

#pragma unroll
        for (int mt = 0; mt < 2; mt++) {
            int jr = j0w + mt * 16;

            uint32_t af[8][4];
#pragma unroll
            for (int k8 = 0; k8 < 8; k8++) {
                const float* sr = sS + (jr + g) * SST + k8 * 8 + tig;
                const float* sr8 = sr + 8 * SST;
                af[k8][0] = tf32_cvt(sr[0]);
                af[k8][1] = tf32_cvt(sr8[0]);
                af[k8][2] = tf32_cvt(sr[4]);
                af[k8][3] = tf32_cvt(sr8[4]);
            }

            float oacc[8][4];
#pragma unroll
            for (int n2 = 0; n2 < 8; n2++)
#pragma unroll
                for (int q = 0; q < 4; q++) oacc[n2][q] = 0.f;

#pragma unroll
            for (int nc = 0; nc < 4; nc++) {
                float hacc[4][4];
#pragma unroll
                for (int nt = 0; nt < 4; nt++)
#pragma unroll
                    for (int q = 0; q < 4; q++) hacc[nt][q] = 0.f;

#pragma unroll
                for (int k8 = 0; k8 < 8; k8++) {
#pragma unroll
                    for (int nt = 0; nt < 4; nt++) {
                        float2 bb = w1f[(k8 * 16 + nc * 4 + nt) * 32 + lane];
                        mma_tf32(hacc[nt], af[k8][0], af[k8][1], af[k8][2],
                                 af[k8][3], __float_as_uint(bb.x),
                                 __float_as_uint(bb.y));
                    }
                }
#pragma unroll
                for (int nt = 0; nt < 4; nt++) {
                    int kt = nc * 4 + nt;
                    float m0 = mishf(hacc[nt][0]);
                    float m1 = mishf(hacc[nt][1]);
                    float m2 = mishf(hacc[nt][2]);
                    float m3 = mishf(hacc[nt][3]);
                    __syncwarp();
                    *reinterpret_cast<float2*>(&stg[g * 10 + 2 * tig]) =
                        make_float2(m0, m1);
                    *reinterpret_cast<float2*>(&stg[(g + 8) * 10 + 2 * tig]) =
                        make_float2(m2, m3);
                    __syncwarp();
                    uint32_t a0 = tf32_cvt(stg[g * 10 + tig]);
                    uint32_t a1 = tf32_cvt(stg[(g + 8) * 10 + tig]);
                    uint32_t a2 = tf32_cvt(stg[g * 10 + tig + 4]);
                    uint32_t a3 = tf32_cvt(stg[(g + 8) * 10 + tig + 4]);
#pragma unroll
                    for (int n2 = 0; n2 < 8; n2++) {
                        float2 bb = w2f[(kt * 8 + n2) * 32 + lane];
                        mma_tf32(oacc[n2], a0, a1, a2, a3,
                                 __float_as_uint(bb.x), __float_as_uint(bb.y));
                    }
                }
            }
#pragma unroll
            for (int n2 = 0; n2 < 8; n2++) {
                int c0 = n2 * 8 + 2 * tig;
                float2 bia = *reinterpret_cast<const float2*>(&sm[OFF1_BM2 + c0]);
                *reinterpret_cast<float2*>(&sS[(jr + g) * SST + c0]) =
                    make_float2(oacc[n2][0] + bia.x, oacc[n2][1] + bia.y);
                *reinterpret_cast<float2*>(&sS[(jr + g + 8) * SST + c0]) =
                    make_float2(oacc[n2][2] + bia.x, oacc[n2][3] + bia.y);
            }
        }
    }
    __syncthreads();

    // chunk-local stats; overwrite sS with p = exp(s - m)
#pragma unroll
    for (int r = 0; r < 2; r++) {
        int job = t + 512 * r;
        int il = job >> 6, ch = job & 63;
        float m = -1e30f;
#pragma unroll 4
        for (int jj = 0; jj < 32; jj++)
            m = fmaxf(m, sS[(il * 32 + jj) * SST + ch]);
        float s = 0.f;
#pragma unroll 4
        for (int jj = 0; jj < 32; jj++) {
            float e = __expf(sS[(il * 32 + jj) * SST + ch] - m);
            sS[(il * 32 + jj) * SST + ch] = e;
            s += e;
        }
        size_t sb = (((size_t)(cb * 16 + chunk)) * 16 + il) * 64 + ch;
        g_smax[sb] = m;
        g_ssum[sb] = s;
    }
    __syncthreads();
    // writeback: g_S layout [b][it][j][ih][il8][ch64] — pure float4 LDS + STG
    {
        float4* gS4 = reinterpret_cast<float4*>(g_S);
        for (int k = 0; k < 16; k++) {
            int fl = t + 512 * k;  // 8192 jobs = 32jj x 2ih x 8il x 16c4
            int jj = fl >> 8, r = fl & 255;
            int ih = r >> 7, r2 = r & 127;
            int il = r2 >> 4, c4 = r2 & 15;
            float4 v = *reinterpret_cast<const float4*>(
                &sS[((ih * 8 + il) * 32 + jj) * SST + c4 * 4]);
            gS4[((size_t)(cb * 512 + j0 + jj) * 2 + ih) * 128 + il * 16 + c4] = v;
        }
    }
}

// ---------------- K2: partial attend (i-split 8, j-split 128) --------------
#define OFF2_P 0        /* 16*64*12 = 12288 */
#define OFF2_F 12288    /* [4 c2][8 il][64 ch] = 2048 */
#define OFF2_DIS 14336  /* 16*8*3 = 384 */
#define K2_FLOATS 14720
#define K2_BYTES (K2_FLOATS * 4)

__global__ __launch_bounds__(512, 2) void attend_partial(
    const float* __restrict__ dis) {
    extern __shared__ float sm[];
    float* sP = sm + OFF2_P;
    float* sF = sm + OFF2_F;
    float* sDis = sm + OFF2_DIS;

    int t = threadIdx.x;
    int it2 = blockIdx.x, b = blockIdx.y, js = blockIdx.z;
    int it = it2 >> 1, ih = it2 & 1;
    int i0 = it2 * 8;
    int cb = b * 8 + it;

    // scale factors f = exp(m_c - gmax), laid out [c2][il8][ch64]
    {
        int il = t >> 6, ch = t & 63;
        size_t base = (size_t)cb * 16384 + (ih * 8 + il) * 64 + ch;
        float gm = -1e30f;
#pragma unroll
        for (int c = 0; c < 16; c++) gm = fmaxf(gm, g_smax[base + c * 1024]);
#pragma unroll
        for (int c2 = 0; c2 < 4; c2++) {
            float m = g_smax[base + (js * 4 + c2) * 1024];
            sF[c2 * 512 + il * 64 + ch] = __expf(m - gm);
        }
    }

    int hB = t >> 4, d2 = t & 15;
    float2 accV[8];
#pragma unroll
    for (int il = 0; il < 8; il++) accV[il] = make_float2(0.f, 0.f);
    float accD[2] = {0.f, 0.f};
    int ilD[2], d3D[2], h2D[2];
#pragma unroll
    for (int r = 0; r < 2; r++) {
        int jd = t + 512 * r;
        ilD[r] = jd / 96;
        int rem = jd - ilD[r] * 96;
        d3D[r] = rem >> 5;
        h2D[r] = rem & 31;
    }

    for (int chunk = 0; chunk < 8; chunk++) {
        int j0c = js * 128 + chunk * 16;
        int c2 = chunk >> 1;
        __syncthreads();
        // phase A: sP = p * f (coalesced g_S reads, scalar transpose STS)
        {
            const float4* gS4 = reinterpret_cast<const float4*>(g_S);
#pragma unroll
            for (int k = 0; k < 4; k++) {
                int fl = t + 512 * k;  // 2048 jobs = 16jl x 8il x 16c4
                int jl = fl >> 7, r = fl & 127;
                int il = r >> 4, c4 = r & 15;
                float4 p4 = gS4[((size_t)(cb * 512 + j0c + jl) * 2 + ih) * 128 +
                                il * 16 + c4];
                float4 f4 = *reinterpret_cast<const float4*>(
                    &sF[c2 * 512 + il * 64 + c4 * 4]);
                int rowb = (jl * 64 + c4 * 4) * 12 + il;
                sP[rowb] = p4.x * f4.x;
                sP[rowb + 12] = p4.y * f4.y;
                sP[rowb + 24] = p4.z * f4.z;
                sP[rowb + 36] = p4.w * f4.w;
            }
            if (t < 384) {
                int j = t / 24, rem = t - j * 24;
                int il2 = rem / 3, d3 = rem - il2 * 3;
                sDis[t] = dis[((size_t)(b * 512 + j0c + j) * 128 + i0 + il2) * 3 + d3];
            }
        }
        __syncthreads();
        // phase B: AV accumulation
#pragma unroll 4
        for (int j = 0; j < 16; j++) {
            float2 cv = *reinterpret_cast<const float2*>(
                &g_CV[(size_t)(b * 512 + j0c + j) * 1024 + hB * 32 + d2 * 2]);
            const float* pr = sP + (j * 64 + hB) * 12;
            float4 p4a = *reinterpret_cast<const float4*>(&pr[0]);
            float4 p4b = *reinterpret_cast<const float4*>(&pr[4]);
            accV[0].x += p4a.x * cv.x;
            accV[0].y += p4a.x * cv.y;
            accV[1].x += p4a.y * cv.x;
            accV[1].y += p4a.y * cv.y;
            accV[2].x += p4a.z * cv.x;
            accV[2].y += p4a.z * cv.y;
            accV[3].x += p4a.w * cv.x;
            accV[3].y += p4a.w * cv.y;
            accV[4].x += p4b.x * cv.x;
            accV[4].y += p4b.x * cv.y;
            accV[5].x += p4b.y * cv.x;
            accV[5].y += p4b.y * cv.y;
            accV[6].x += p4b.z * cv.x;
            accV[6].y += p4b.z * cv.y;
            accV[7].x += p4b.w * cv.x;
            accV[7].y += p4b.w * cv.y;
        }
        // phase C: distance accumulation
#pragma unroll
        for (int r = 0; r < 2; r++) {
            int jd = t + 512 * r;
            if (jd < 768) {
                float a = accD[r];
                int il = ilD[r], d3 = d3D[r], h2 = h2D[r];
#pragma unroll 4
                for (int j = 0; j < 16; j++)
                    a += sP[(j * 64 + 32 + h2) * 12 + il] * sDis[j * 24 + il * 3 + d3];
                accD[r] = a;
            }
        }
    }
    // write unnormalized partials
    {
        size_t pb = ((size_t)cb * 4 + js) * 16384;
#pragma unroll
        for (int il = 0; il < 8; il++) {
            *reinterpret_cast<float2*>(
                &g_pAV[pb + (ih * 8 + il) * 1024 + hB * 32 + d2 * 2]) = accV[il];
        }
        size_t db = ((size_t)cb * 4 + js) * 1536;
#pragma unroll
        for (int r = 0; r < 2; r++) {
            int jd = t + 512 * r;
            if (jd < 768) {
                int jobG = (ih * 8 + ilD[r]) * 96 + d3D[r] * 32 + h2D[r];
                g_pD[db + jobG] = accD[r];
            }
        }
    }
}

// ---------------- K3: reduce + epilogues (i-split, direct W_o LDG) ---------
#define OFF3_AV 0       /* 8*1024 = 8192 */
#define OFF3_INV 8192   /* 512 */
#define OFF3_OD 8704    /* 768 */
#define OFF3_HD 9472    /* 1536 */
#define K3_FLOATS 11008
#define K3_BYTES (K3_FLOATS * 4)

__global__ __launch_bounds__(512, 2) void reduce_kernel(
    const float* __restrict__ W_o, const float* __restrict__ b_o,
    const float* __restrict__ W_d1, const float* __restrict__ b_d1,
    const float* __restrict__ W_d2, const float* __restrict__ b_d2,
    float* __restrict__ out) {
    extern __shared__ float sm[];
    float* sAV = sm + OFF3_AV;
    float* sINV = sm + OFF3_INV;
    float* sOd = sm + OFF3_OD;
    float* sHd = sm + OFF3_HD;

    int t = threadIdx.x;
    int it2 = blockIdx.x, b = blockIdx.y;
    int it = it2 >> 1, ih = it2 & 1;
    int i0 = it2 * 8;
    int cb = b * 8 + it;

    // softmax 1/sum for this i-half
    {
        int il = t >> 6, ch = t & 63;
        size_t base = (size_t)cb * 16384 + (ih * 8 + il) * 64 + ch;
        float gm = -1e30f;
#pragma unroll
        for (int c = 0; c < 16; c++) gm = fmaxf(gm, g_smax[base + c * 1024]);
        float S = 0.f;
#pragma unroll
        for (int c = 0; c < 16; c++)
            S += g_ssum[base + c * 1024] * __expf(g_smax[base + c * 1024] - gm);
        sINV[il * 64 + ch] = 1.f / S;
    }
    __syncthreads();

    // AV reduce over 4 js partials, normalize into sAV (8 il)
    {
        int hB = t >> 4, d2 = t & 15;
        size_t pb = (size_t)cb * 4 * 16384;
#pragma unroll
        for (int il = 0; il < 8; il++) {
            int off = (ih * 8 + il) * 1024 + hB * 32 + d2 * 2;
            float2 a0 = *reinterpret_cast<const float2*>(&g_pAV[pb + off]);
            float2 a1 = *reinterpret_cast<const float2*>(&g_pAV[pb + 16384 + off]);
            float2 a2 = *reinterpret_cast<const float2*>(&g_pAV[pb + 32768 + off]);
            float2 a3 = *reinterpret_cast<const float2*>(&g_pAV[pb + 49152 + off]);
            float inv = sINV[il * 64 + hB];
            *reinterpret_cast<float2*>(&sAV[il * 1024 + hB * 32 + d2 * 2]) =
                make_float2((a0.x + a1.x + a2.x + a3.x) * inv,
                            (a0.y + a1.y + a2.y + a3.y) * inv);
        }
    }
    // dis reduce (768 jobs for 8 il)
    {
        size_t db = (size_t)cb * 4 * 1536;
#pragma unroll
        for (int r = 0; r < 2; r++) {
            int jd = t + 512 * r;
            if (jd < 768) {
                int il = jd / 96, rem = jd - il * 96;
                int h2 = rem & 31;
                int jobG = (ih * 8 + il) * 96 + rem;
                float v = g_pD[db + jobG] + g_pD[db + 1536 + jobG] +
                          g_pD[db + 3072 + jobG] + g_pD[db + 4608 + jobG];
                sOd[jd] = v * sINV[il * 64 + 32 + h2];
            }
        }
    }
    __syncthreads();

    // W_o GEMM: direct LDG k-loop, 1 output float4 per thread
    {
        int il = t >> 6, c4 = t & 63;
        float4 acc = reinterpret_cast<const float4*>(b_o)[c4];
        const float4* wo4 = reinterpret_cast<const float4*>(W_o);
        const float* av = sAV + il * 1024;
#pragma unroll 4
        for (int k = 0; k < 1024; k++) {
            float s = av[k];
            float4 wv = wo4[(size_t)k * 64 + c4];
            acc.x += s * wv.x;
            acc.y += s * wv.y;
            acc.z += s * wv.z;
            acc.w += s * wv.w;
        }
        reinterpret_cast<float4*>(out)[(size_t)(b * 128 + i0 + il) * 64 + c4] = acc;
    }
    __syncthreads();

    // dis MLP (8 il): layer 1 -> 1536 jobs
#pragma unroll
    for (int r = 0; r < 3; r++) {
        int job = t + 512 * r;
        int u = job & 63, rem = job >> 6;
        int il = rem / 3, d3 = rem - il * 3;
        float a = b_d1[u];
#pragma unroll
        for (int k = 0; k < 32; k++) a += sOd[il * 96 + d3 * 32 + k] * W_d1[k * 64 + u];
        sHd[(il * 3 + d3) * 64 + u] = mishf(a);
    }
    __syncthreads();
    // layer 2 -> 768 jobs
#pragma unroll
    for (int r = 0; r < 2; r++) {
        int jd = t + 512 * r;
        if (jd < 768) {
            int h = jd & 31, rem = jd >> 5;
            int il = rem / 3, d3 = rem - il * 3;
            float a = b_d2[h];
#pragma unroll
            for (int k = 0; k < 64; k++)
                a += sHd[(il * 3 + d3) * 64 + k] * W_d2[k * 32 + h];
            out[524288 + ((size_t)(b * 128 + i0 + il) * 3 + d3) * 32 + h] = a;
        }
    }
}

// ---------------- launch ----------------
extern "C" void kernel_launch(void* const* d_in, const int* in_sizes, int n_in,
                              void* d_out, int out_size) {
    const float* x = (const float*)d_in[0];
    const float* context = (const float*)d_in[1];
    const float* dis = (const float*)d_in[2];
    const float* dis_emb = (const float*)d_in[3];
    int wb = (n_in == 17) ? 4 : 6;
    const float* W_qk = (const float*)d_in[wb + 0];
    const float* W_cqk = (const float*)d_in[wb + 2];
    const float* W_cv = (const float*)d_in[wb + 3];
    const float* W_m1 = (const float*)d_in[wb + 4];
    const float* W_m2 = (const float*)d_in[wb + 5];
    const float* b_m2 = (const float*)d_in[wb + 6];
    const float* W_o = (const float*)d_in[wb + 7];
    const float* b_o = (const float*)d_in[wb + 8];
    const float* W_d1 = (const float*)d_in[wb + 9];
    const float* b_d1 = (const float*)d_in[wb + 10];
    const float* W_d2 = (const float*)d_in[wb + 11];
    const float* b_d2 = (const float*)d_in[wb + 12];
    float* out = (float*)d_out;

    proj_fused<<<dim3(128, 8, 3), 256, PROJ_SMEM_BYTES>>>(x, context, W_qk,
                                                          W_cqk, W_cv);

    cudaFuncSetAttribute(score_kernel, cudaFuncAttributeMaxDynamicSharedMemorySize,
                         K1_BYTES);
    cudaFuncSetAttribute(attend_partial, cudaFuncAttributeMaxDynamicSharedMemorySize,
                         K2_BYTES);
    cudaFuncSetAttribute(reduce_kernel, cudaFuncAttributeMaxDynamicSharedMemorySize,
                         K3_BYTES);
    score_kernel<<<dim3(16, 8, 16), 512, K1_BYTES>>>(dis_emb, W_m1, W_m2, b_m2);
    attend_partial<<<dim3(16, 16, 4), 512, K2_BYTES>>>(dis);
    reduce_kernel<<<dim3(16, 16), 512, K3_BYTES>>>(W_o, b_o, W_d1, b_d1, W_d2,
                                                   b_d2, out);
}

// round 17
// speedup vs baseline: 1.0242x; 1.0242x over previous
#include <cuda_runtime.h>
#include <math.h>
#include <stdint.h>

#define BATCH 16
#define LQ 128
#define LP 512
#define H 32
#define DH 32
#define SST 68                     /* padded row stride for s tile */
#define SCALE 0.17677669529663687f /* 32^-0.5 */

// ---------------- scratch (static device arrays; no allocs) ----------------
__device__ float g_QK[2048 * 1024];        // [n][h*32+d]
__device__ float g_CQKt[16 * 1024 * 512];  // [b][c][j]  (transposed)
__device__ float g_CV[8192 * 1024];        // [b*512+j][h*32+d]
__device__ float g_S[16 * 8 * 512 * 16 * 64];    // [b][it][j][ih][ch][il8] : p
__device__ float g_smax[16 * 8 * 16 * 16 * 64];  // [b][it][chunk][il][ch]
__device__ float g_ssum[16 * 8 * 16 * 16 * 64];
__device__ float g_pAV[16 * 8 * 4 * 16 * 1024];  // [b][it][js][il][c]
__device__ float g_pD[16 * 8 * 4 * 1536];        // [b][it][js][job]

// fast mish: x * (t^2-1)/(t^2+1), t = 1+e^x
__device__ __forceinline__ float mishf(float x) {
    if (x > 20.f) return x;
    float t = 1.f + __expf(x);
    float t2 = t * t;
    return x * __fdividef(t2 - 1.f, t2 + 1.f);
}

__device__ __forceinline__ uint32_t tf32_cvt(float x) {
    uint32_t r;
    asm("cvt.rna.tf32.f32 %0, %1;" : "=r"(r) : "f"(x));
    return r;
}

__device__ __forceinline__ void mma_tf32(float* d, uint32_t a0, uint32_t a1,
                                         uint32_t a2, uint32_t a3, uint32_t b0,
                                         uint32_t b1) {
    asm volatile(
        "mma.sync.aligned.m16n8k8.row.col.f32.tf32.tf32.f32 "
        "{%0,%1,%2,%3}, {%4,%5,%6,%7}, {%8,%9}, {%0,%1,%2,%3};\n"
        : "+f"(d[0]), "+f"(d[1]), "+f"(d[2]), "+f"(d[3])
        : "r"(a0), "r"(a1), "r"(a2), "r"(a3), "r"(b0), "r"(b1));
}

// ---------------- fused projection GEMM (tf32 mma) --------------------------
#define PROJ_SMEM_FLOATS 8448
#define PROJ_SMEM_BYTES (PROJ_SMEM_FLOATS * 4)

__global__ __launch_bounds__(256) void proj_fused(
    const float* __restrict__ x, const float* __restrict__ ctx,
    const float* __restrict__ W_qk, const float* __restrict__ W_cqk,
    const float* __restrict__ W_cv) {
    int mode = blockIdx.z;
    if (mode == 0 && blockIdx.x >= 32) return;

    extern __shared__ float smp[];
    float* sA = smp;              // [64][36]
    float* sW = smp + 64 * 36;    // [32][132]
    float* sC = smp;              // [64][132] alias (mode-1 epilogue)

    const float* A = (mode == 0) ? x : ctx;
    const float* W = (mode == 0) ? W_qk : (mode == 1 ? W_cqk : W_cv);
    float* outp = (mode == 0) ? g_QK : (mode == 1 ? g_CQKt : g_CV);

    int t = threadIdx.x, lane = t & 31, w = t >> 5;
    int m0 = blockIdx.x * 64, n0 = blockIdx.y * 128;
    int wm = w >> 1, wn = w & 1;
    int g = lane >> 2, tig = lane & 3;

    float acc[8][4];
#pragma unroll
    for (int nt = 0; nt < 8; nt++)
#pragma unroll
        for (int q = 0; q < 4; q++) acc[nt][q] = 0.f;

    for (int k0 = 0; k0 < 256; k0 += 32) {
#pragma unroll
        for (int f = 0; f < 2; f++) {
            int job = t + 256 * f;
            int r = job >> 3, c4 = job & 7;
            float4 v = reinterpret_cast<const float4*>(A)[(size_t)(m0 + r) * 64 + (k0 >> 2) + c4];
            *reinterpret_cast<float4*>(&sA[r * 36 + c4 * 4]) = v;
        }
#pragma unroll
        for (int f = 0; f < 4; f++) {
            int job = t + 256 * f;
            int kk = job >> 5, c4 = job & 31;
            float4 v = reinterpret_cast<const float4*>(W)[(size_t)(k0 + kk) * 256 + (n0 >> 2) + c4];
            *reinterpret_cast<float4*>(&sW[kk * 132 + c4 * 4]) = v;
        }
        __syncthreads();
#pragma unroll
        for (int k8 = 0; k8 < 4; k8++) {
            const float* ap = sA + (wm * 16 + g) * 36 + k8 * 8 + tig;
            uint32_t a0 = __float_as_uint(ap[0]);
            uint32_t a1 = __float_as_uint(ap[8 * 36]);
            uint32_t a2 = __float_as_uint(ap[4]);
            uint32_t a3 = __float_as_uint(ap[8 * 36 + 4]);
#pragma unroll
            for (int nt = 0; nt < 8; nt++) {
                const float* bp = sW + (k8 * 8 + tig) * 132 + wn * 64 + nt * 8 + g;
                uint32_t b0 = __float_as_uint(bp[0]);
                uint32_t b1 = __float_as_uint(bp[4 * 132]);
                mma_tf32(acc[nt], a0, a1, a2, a3, b0, b1);
            }
        }
        __syncthreads();
    }

    if (mode != 1) {
#pragma unroll
        for (int nt = 0; nt < 8; nt++) {
            int col = n0 + wn * 64 + nt * 8 + 2 * tig;
            int row = m0 + wm * 16 + g;
            *reinterpret_cast<float2*>(&outp[(size_t)row * 1024 + col]) =
                make_float2(acc[nt][0], acc[nt][1]);
            *reinterpret_cast<float2*>(&outp[(size_t)(row + 8) * 1024 + col]) =
                make_float2(acc[nt][2], acc[nt][3]);
        }
    } else {
#pragma unroll
        for (int nt = 0; nt < 8; nt++) {
            int col = wn * 64 + nt * 8 + 2 * tig;
            int row = wm * 16 + g;
            *reinterpret_cast<float2*>(&sC[row * 132 + col]) =
                make_float2(acc[nt][0], acc[nt][1]);
            *reinterpret_cast<float2*>(&sC[(row + 8) * 132 + col]) =
                make_float2(acc[nt][2], acc[nt][3]);
        }
        __syncthreads();
        int bb = m0 >> 9, jbase = m0 & 511;
#pragma unroll
        for (int f = 0; f < 32; f++) {
            int job = t + 256 * f;
            int cc = job >> 6, jj = job & 63;
            outp[((size_t)bb * 1024 + n0 + cc) * 512 + jbase + jj] = sC[jj * 132 + cc];
        }
    }
}

// ---------------- K1: score kernel -----------------------------------------
#define OFF1_W1F 34816
#define OFF1_W2F 43008
#define OFF1_BM2 51200
#define OFF1_STG 51264
#define K1_FLOATS 53824
#define K1_BYTES (K1_FLOATS * 4)

__global__ __launch_bounds__(512, 1) void score_kernel(
    const float* __restrict__ dis_emb, const float* __restrict__ W_m1,
    const float* __restrict__ W_m2, const float* __restrict__ b_m2) {
    extern __shared__ float sm[];
    float* cqks = sm;  // [1024][33]
    float* sS = sm;    // [512][68] after sim
    float2* w1f = reinterpret_cast<float2*>(sm + OFF1_W1F);
    float2* w2f = reinterpret_cast<float2*>(sm + OFF1_W2F);

    int t = threadIdx.x, lane = t & 31, w = t >> 5;
    int chunk = blockIdx.x, it = blockIdx.y, b = blockIdx.z;
    int j0 = chunk * 32, i0 = it * 16;
    int g = lane >> 2, tig = lane & 3;
    int cb = b * 8 + it;

    // stage CQK chunk [1024][33]
    {
        const float* src = g_CQKt + (size_t)b * 1024 * 512 + j0;
        for (int k = 0; k < 64; k++) {
            int fl = t + 512 * k;
            int c = fl >> 5, jj = fl & 31;
            cqks[c * 33 + jj] = src[(size_t)c * 512 + jj];
        }
    }
    // weight fragments (tf32 pre-rounded, rna — done once)
#pragma unroll
    for (int p = 0; p < 8; p++) {
        int idx = t + 512 * p;
        int fi = idx >> 5, ln = idx & 31;
        int gg = ln >> 2, tt = ln & 3;
        {
            int k8 = fi >> 4, nt = fi & 15;
            float b0 = W_m1[(k8 * 8 + tt) * 128 + nt * 8 + gg];
            float b1 = W_m1[(k8 * 8 + tt + 4) * 128 + nt * 8 + gg];
            w1f[idx] = make_float2(__uint_as_float(tf32_cvt(b0)),
                                   __uint_as_float(tf32_cvt(b1)));
        }
        {
            int kt = fi >> 3, n2 = fi & 7;
            float c0 = W_m2[(kt * 8 + tt) * 64 + n2 * 8 + gg];
            float c1 = W_m2[(kt * 8 + tt + 4) * 64 + n2 * 8 + gg];
            w2f[idx] = make_float2(__uint_as_float(tf32_cvt(c0)),
                                   __uint_as_float(tf32_cvt(c1)));
        }
    }
    if (t < 64) sm[OFF1_BM2 + t] = b_m2[t];
    __syncthreads();

    // ---- sim via mma.sync tf32: per head D[32j,16i] = CQK @ QK^T ----
    float Dh[2][2][2][4];
    {
        const float* qkb = g_QK + (size_t)(b * 128 + i0) * 1024;
#pragma unroll
        for (int hh = 0; hh < 2; hh++) {
            int h = w * 2 + hh;
#pragma unroll
            for (int mt = 0; mt < 2; mt++)
#pragma unroll
                for (int nt = 0; nt < 2; nt++)
#pragma unroll
                    for (int q = 0; q < 4; q++) Dh[hh][mt][nt][q] = 0.f;
#pragma unroll
            for (int kt = 0; kt < 4; kt++) {
                const float* ap = cqks + (h * 32 + kt * 8 + tig) * 33 + g;
                uint32_t a00 = __float_as_uint(ap[0]);
                uint32_t a01 = __float_as_uint(ap[8]);
                uint32_t a02 = __float_as_uint(ap[4 * 33]);
                uint32_t a03 = __float_as_uint(ap[4 * 33 + 8]);
                uint32_t a10 = __float_as_uint(ap[16]);
                uint32_t a11 = __float_as_uint(ap[24]);
                uint32_t a12 = __float_as_uint(ap[4 * 33 + 16]);
                uint32_t a13 = __float_as_uint(ap[4 * 33 + 24]);
#pragma unroll
                for (int nt = 0; nt < 2; nt++) {
                    const float* bp = qkb + (size_t)(nt * 8 + g) * 1024 + h * 32 + kt * 8 + tig;
                    uint32_t b0 = __float_as_uint(__ldg(bp));
                    uint32_t b1 = __float_as_uint(__ldg(bp + 4));
                    mma_tf32(Dh[hh][0][nt], a00, a01, a02, a03, b0, b1);
                    mma_tf32(Dh[hh][1][nt], a10, a11, a12, a13, b0, b1);
                }
            }
        }
    }
    __syncthreads();  // all cqks reads done; region becomes sS

    // scatter sim into sS; load dis_emb channels
    {
#pragma unroll
        for (int hh = 0; hh < 2; hh++) {
            int h = w * 2 + hh;
#pragma unroll
            for (int mt = 0; mt < 2; mt++)
#pragma unroll
                for (int nt = 0; nt < 2; nt++) {
                    int jr = mt * 16 + g;
                    int ic = nt * 8 + 2 * tig;
                    sS[(ic * 32 + jr) * SST + h] = Dh[hh][mt][nt][0] * SCALE;
                    sS[((ic + 1) * 32 + jr) * SST + h] = Dh[hh][mt][nt][1] * SCALE;
                    sS[(ic * 32 + jr + 8) * SST + h] = Dh[hh][mt][nt][2] * SCALE;
                    sS[((ic + 1) * 32 + jr + 8) * SST + h] = Dh[hh][mt][nt][3] * SCALE;
                }
        }
        const float4* de4 = reinterpret_cast<const float4*>(dis_emb);
        for (int k = 0; k < 8; k++) {
            int fl = t + 512 * k;
            int jj = fl >> 7, r = fl & 127, il = r >> 3, h4 = r & 7;
            float4 v = de4[((size_t)(b * 512 + j0 + jj) * 128 + i0 + il) * 8 + h4];
            *reinterpret_cast<float4*>(&sS[(il * 32 + jj) * SST + 32 + h4 * 4]) = v;
        }
    }
    __syncthreads();

    // ---- MLP via mma.sync tf32 (A-frags hoisted, smem staging remap) ----
    {
        int j0w = w * 32;
        float* stg = sm + OFF1_STG + w * 160;  // 16 rows x stride 10

#pragma unroll
        for (int mt = 0; mt < 2; mt++) {
            int jr = j0w + mt * 16;

            uint32_t af[8][4];
#pragma unroll
            for (int k8 = 0; k8 < 8; k8++) {
                const float* sr = sS + (jr + g) * SST + k8 * 8 + tig;
                const float* sr8 = sr + 8 * SST;
                af[k8][0] = __float_as_uint(sr[0]);
                af[k8][1] = __float_as_uint(sr8[0]);
                af[k8][2] = __float_as_uint(sr[4]);
                af[k8][3] = __float_as_uint(sr8[4]);
            }

            float oacc[8][4];
#pragma unroll
            for (int n2 = 0; n2 < 8; n2++)
#pragma unroll
                for (int q = 0; q < 4; q++) oacc[n2][q] = 0.f;

#pragma unroll
            for (int nc = 0; nc < 4; nc++) {
                float hacc[4][4];
#pragma unroll
                for (int nt = 0; nt < 4; nt++)
#pragma unroll
                    for (int q = 0; q < 4; q++) hacc[nt][q] = 0.f;

#pragma unroll
                for (int k8 = 0; k8 < 8; k8++) {
#pragma unroll
                    for (int nt = 0; nt < 4; nt++) {
                        float2 bb = w1f[(k8 * 16 + nc * 4 + nt) * 32 + lane];
                        mma_tf32(hacc[nt], af[k8][0], af[k8][1], af[k8][2],
                                 af[k8][3], __float_as_uint(bb.x),
                                 __float_as_uint(bb.y));
                    }
                }
#pragma unroll
                for (int nt = 0; nt < 4; nt++) {
                    int kt = nc * 4 + nt;
                    float m0 = mishf(hacc[nt][0]);
                    float m1 = mishf(hacc[nt][1]);
                    float m2 = mishf(hacc[nt][2]);
                    float m3 = mishf(hacc[nt][3]);
                    __syncwarp();
                    *reinterpret_cast<float2*>(&stg[g * 10 + 2 * tig]) =
                        make_float2(m0, m1);
                    *reinterpret_cast<float2*>(&stg[(g + 8) * 10 + 2 * tig]) =
                        make_float2(m2, m3);
                    __syncwarp();
                    uint32_t a0 = __float_as_uint(stg[g * 10 + tig]);
                    uint32_t a1 = __float_as_uint(stg[(g + 8) * 10 + tig]);
                    uint32_t a2 = __float_as_uint(stg[g * 10 + tig + 4]);
                    uint32_t a3 = __float_as_uint(stg[(g + 8) * 10 + tig + 4]);
#pragma unroll
                    for (int n2 = 0; n2 < 8; n2++) {
                        float2 bb = w2f[(kt * 8 + n2) * 32 + lane];
                        mma_tf32(oacc[n2], a0, a1, a2, a3,
                                 __float_as_uint(bb.x), __float_as_uint(bb.y));
                    }
                }
            }
#pragma unroll
            for (int n2 = 0; n2 < 8; n2++) {
                int c0 = n2 * 8 + 2 * tig;
                float2 bia = *reinterpret_cast<const float2*>(&sm[OFF1_BM2 + c0]);
                *reinterpret_cast<float2*>(&sS[(jr + g) * SST + c0]) =
                    make_float2(oacc[n2][0] + bia.x, oacc[n2][1] + bia.y);
                *reinterpret_cast<float2*>(&sS[(jr + g + 8) * SST + c0]) =
                    make_float2(oacc[n2][2] + bia.x, oacc[n2][3] + bia.y);
            }
        }
    }
    __syncthreads();

    // chunk-local stats; overwrite sS with p = exp(s - m)
#pragma unroll
    for (int r = 0; r < 2; r++) {
        int job = t + 512 * r;
        int il = job >> 6, ch = job & 63;
        float m = -1e30f;
#pragma unroll 4
        for (int jj = 0; jj < 32; jj++)
            m = fmaxf(m, sS[(il * 32 + jj) * SST + ch]);
        float s = 0.f;
#pragma unroll 4
        for (int jj = 0; jj < 32; jj++) {
            float e = __expf(sS[(il * 32 + jj) * SST + ch] - m);
            sS[(il * 32 + jj) * SST + ch] = e;
            s += e;
        }
        size_t sb = (((size_t)(cb * 16 + chunk)) * 16 + il) * 64 + ch;
        g_smax[sb] = m;
        g_ssum[sb] = s;
    }
    __syncthreads();
    // writeback: g_S layout [b][it][j][ih][ch][il8]
    {
        float4* gS4 = reinterpret_cast<float4*>(g_S);
        for (int k = 0; k < 16; k++) {
            int fl = t + 512 * k;  // 8192 float4 jobs = 32jj x 2ih x 64ch x 2il4
            int jj = fl >> 8, r = fl & 255;
            int ih = r >> 7, r2 = r & 127;
            int ch = r2 >> 1, il4 = r2 & 1;
            int ilb = ih * 8 + il4 * 4;
            float4 v;
            v.x = sS[((ilb + 0) * 32 + jj) * SST + ch];
            v.y = sS[((ilb + 1) * 32 + jj) * SST + ch];
            v.z = sS[((ilb + 2) * 32 + jj) * SST + ch];
            v.w = sS[((ilb + 3) * 32 + jj) * SST + ch];
            gS4[(size_t)(cb * 512 + j0 + jj) * 256 + ih * 128 + ch * 2 + il4] = v;
        }
    }
}

// ---------------- K2: partial attend (i-split 8, j-split 128) --------------
#define OFF2_P 0        /* 16*64*12 = 12288 */
#define OFF2_F 12288    /* [4 c2][64 ch][8 il] = 2048 */
#define OFF2_DIS 14336  /* 16*8*3 = 384 */
#define K2_FLOATS 14720
#define K2_BYTES (K2_FLOATS * 4)

__global__ __launch_bounds__(512, 2) void attend_partial(
    const float* __restrict__ dis) {
    extern __shared__ float sm[];
    float* sP = sm + OFF2_P;
    float* sF = sm + OFF2_F;
    float* sDis = sm + OFF2_DIS;

    int t = threadIdx.x;
    int it2 = blockIdx.x, b = blockIdx.y, js = blockIdx.z;
    int it = it2 >> 1, ih = it2 & 1;
    int i0 = it2 * 8;
    int cb = b * 8 + it;

    // scale factors f = exp(m_c - gmax), laid out [c2][ch][il8]
    {
        int il = t >> 6, ch = t & 63;
        size_t base = (size_t)cb * 16384 + (ih * 8 + il) * 64 + ch;
        float gm = -1e30f;
#pragma unroll
        for (int c = 0; c < 16; c++) gm = fmaxf(gm, g_smax[base + c * 1024]);
#pragma unroll
        for (int c2 = 0; c2 < 4; c2++) {
            float m = g_smax[base + (js * 4 + c2) * 1024];
            sF[c2 * 512 + ch * 8 + il] = __expf(m - gm);
        }
    }

    int hB = t >> 4, d2 = t & 15;
    float2 accV[8];
#pragma unroll
    for (int il = 0; il < 8; il++) accV[il] = make_float2(0.f, 0.f);
    float accD[2] = {0.f, 0.f};
    int ilD[2], d3D[2], h2D[2];
#pragma unroll
    for (int r = 0; r < 2; r++) {
        int jd = t + 512 * r;
        ilD[r] = jd / 96;
        int rem = jd - ilD[r] * 96;
        d3D[r] = rem >> 5;
        h2D[r] = rem & 31;
    }

    for (int chunk = 0; chunk < 8; chunk++) {
        int j0c = js * 128 + chunk * 16;
        int c2 = chunk >> 1;
        __syncthreads();
        // phase A: sP = p * f (coalesced g_S reads); stage dis chunk
        {
            const float4* gS4 = reinterpret_cast<const float4*>(g_S);
#pragma unroll
            for (int k = 0; k < 4; k++) {
                int fl = t + 512 * k;
                int jl = fl >> 7, r = fl & 127;
                int ch = r >> 1, il4 = r & 1;
                float4 p4 = gS4[(size_t)(cb * 512 + j0c + jl) * 256 + ih * 128 +
                                ch * 2 + il4];
                float4 f4 = *reinterpret_cast<const float4*>(
                    &sF[c2 * 512 + ch * 8 + il4 * 4]);
                *reinterpret_cast<float4*>(&sP[(jl * 64 + ch) * 12 + il4 * 4]) =
                    make_float4(p4.x * f4.x, p4.y * f4.y, p4.z * f4.z,
                                p4.w * f4.w);
            }
            if (t < 384) {
                int j = t / 24, rem = t - j * 24;
                int il2 = rem / 3, d3 = rem - il2 * 3;
                sDis[t] = dis[((size_t)(b * 512 + j0c + j) * 128 + i0 + il2) * 3 + d3];
            }
        }
        __syncthreads();
        // phase B: AV accumulation
#pragma unroll 4
        for (int j = 0; j < 16; j++) {
            float2 cv = *reinterpret_cast<const float2*>(
                &g_CV[(size_t)(b * 512 + j0c + j) * 1024 + hB * 32 + d2 * 2]);
            const float* pr = sP + (j * 64 + hB) * 12;
            float4 p4a = *reinterpret_cast<const float4*>(&pr[0]);
            float4 p4b = *reinterpret_cast<const float4*>(&pr[4]);
            accV[0].x += p4a.x * cv.x;
            accV[0].y += p4a.x * cv.y;
            accV[1].x += p4a.y * cv.x;
            accV[1].y += p4a.y * cv.y;
            accV[2].x += p4a.z * cv.x;
            accV[2].y += p4a.z * cv.y;
            accV[3].x += p4a.w * cv.x;
            accV[3].y += p4a.w * cv.y;
            accV[4].x += p4b.x * cv.x;
            accV[4].y += p4b.x * cv.y;
            accV[5].x += p4b.y * cv.x;
            accV[5].y += p4b.y * cv.y;
            accV[6].x += p4b.z * cv.x;
            accV[6].y += p4b.z * cv.y;
            accV[7].x += p4b.w * cv.x;
            accV[7].y += p4b.w * cv.y;
        }
        // phase C: distance accumulation
#pragma unroll
        for (int r = 0; r < 2; r++) {
            int jd = t + 512 * r;
            if (jd < 768) {
                float a = accD[r];
                int il = ilD[r], d3 = d3D[r], h2 = h2D[r];
#pragma unroll 4
                for (int j = 0; j < 16; j++)
                    a += sP[(j * 64 + 32 + h2) * 12 + il] * sDis[j * 24 + il * 3 + d3];
                accD[r] = a;
            }
        }
    }
    // write unnormalized partials
    {
        size_t pb = ((size_t)cb * 4 + js) * 16384;
#pragma unroll
        for (int il = 0; il < 8; il++) {
            *reinterpret_cast<float2*>(
                &g_pAV[pb + (ih * 8 + il) * 1024 + hB * 32 + d2 * 2]) = accV[il];
        }
        size_t db = ((size_t)cb * 4 + js) * 1536;
#pragma unroll
        for (int r = 0; r < 2; r++) {
            int jd = t + 512 * r;
            if (jd < 768) {
                int jobG = (ih * 8 + ilD[r]) * 96 + d3D[r] * 32 + h2D[r];
                g_pD[db + jobG] = accD[r];
            }
        }
    }
}

// ---------------- K3: reduce + epilogues (i-split, direct W_o LDG) ---------
#define OFF3_AV 0       /* 8*1024 = 8192 */
#define OFF3_INV 8192   /* 512 */
#define OFF3_OD 8704    /* 768 */
#define OFF3_HD 9472    /* 1536 */
#define K3_FLOATS 11008
#define K3_BYTES (K3_FLOATS * 4)

__global__ __launch_bounds__(512, 2) void reduce_kernel(
    const float* __restrict__ W_o, const float* __restrict__ b_o,
    const float* __restrict__ W_d1, const float* __restrict__ b_d1,
    const float* __restrict__ W_d2, const float* __restrict__ b_d2,
    float* __restrict__ out) {
    extern __shared__ float sm[];
    float* sAV = sm + OFF3_AV;
    float* sINV = sm + OFF3_INV;
    float* sOd = sm + OFF3_OD;
    float* sHd = sm + OFF3_HD;

    int t = threadIdx.x;
    int it2 = blockIdx.x, b = blockIdx.y;
    int it = it2 >> 1, ih = it2 & 1;
    int i0 = it2 * 8;
    int cb = b * 8 + it;

    // softmax 1/sum for this i-half
    {
        int il = t >> 6, ch = t & 63;
        size_t base = (size_t)cb * 16384 + (ih * 8 + il) * 64 + ch;
        float gm = -1e30f;
#pragma unroll
        for (int c = 0; c < 16; c++) gm = fmaxf(gm, g_smax[base + c * 1024]);
        float S = 0.f;
#pragma unroll
        for (int c = 0; c < 16; c++)
            S += g_ssum[base + c * 1024] * __expf(g_smax[base + c * 1024] - gm);
        sINV[il * 64 + ch] = 1.f / S;
    }
    __syncthreads();

    // AV reduce over 4 js partials, normalize into sAV (8 il)
    {
        int hB = t >> 4, d2 = t & 15;
        size_t pb = (size_t)cb * 4 * 16384;
#pragma unroll
        for (int il = 0; il < 8; il++) {
            int off = (ih * 8 + il) * 1024 + hB * 32 + d2 * 2;
            float2 a0 = *reinterpret_cast<const float2*>(&g_pAV[pb + off]);
            float2 a1 = *reinterpret_cast<const float2*>(&g_pAV[pb + 16384 + off]);
            float2 a2 = *reinterpret_cast<const float2*>(&g_pAV[pb + 32768 + off]);
            float2 a3 = *reinterpret_cast<const float2*>(&g_pAV[pb + 49152 + off]);
            float inv = sINV[il * 64 + hB];
            *reinterpret_cast<float2*>(&sAV[il * 1024 + hB * 32 + d2 * 2]) =
                make_float2((a0.x + a1.x + a2.x + a3.x) * inv,
                            (a0.y + a1.y + a2.y + a3.y) * inv);
        }
    }
    // dis reduce (768 jobs for 8 il)
    {
        size_t db = (size_t)cb * 4 * 1536;
#pragma unroll
        for (int r = 0; r < 2; r++) {
            int jd = t + 512 * r;
            if (jd < 768) {
                int il = jd / 96, rem = jd - il * 96;
                int h2 = rem & 31;
                int jobG = (ih * 8 + il) * 96 + rem;
                float v = g_pD[db + jobG] + g_pD[db + 1536 + jobG] +
                          g_pD[db + 3072 + jobG] + g_pD[db + 4608 + jobG];
                sOd[jd] = v * sINV[il * 64 + 32 + h2];
            }
        }
    }
    __syncthreads();

    // W_o GEMM: direct LDG k-loop, 1 output float4 per thread
    {
        int il = t >> 6, c4 = t & 63;
        float4 acc = reinterpret_cast<const float4*>(b_o)[c4];
        const float4* wo4 = reinterpret_cast<const float4*>(W_o);
        const float* av = sAV + il * 1024;
#pragma unroll 4
        for (int k = 0; k < 1024; k++) {
            float s = av[k];
            float4 wv = wo4[(size_t)k * 64 + c4];
            acc.x += s * wv.x;
            acc.y += s * wv.y;
            acc.z += s * wv.z;
            acc.w += s * wv.w;
        }
        reinterpret_cast<float4*>(out)[(size_t)(b * 128 + i0 + il) * 64 + c4] = acc;
    }
    __syncthreads();

    // dis MLP (8 il): layer 1 -> 1536 jobs
#pragma unroll
    for (int r = 0; r < 3; r++) {
        int job = t + 512 * r;
        int u = job & 63, rem = job >> 6;
        int il = rem / 3, d3 = rem - il * 3;
        float a = b_d1[u];
#pragma unroll
        for (int k = 0; k < 32; k++) a += sOd[il * 96 + d3 * 32 + k] * W_d1[k * 64 + u];
        sHd[(il * 3 + d3) * 64 + u] = mishf(a);
    }
    __syncthreads();
    // layer 2 -> 768 jobs
#pragma unroll
    for (int r = 0; r < 2; r++) {
        int jd = t + 512 * r;
        if (jd < 768) {
            int h = jd & 31, rem = jd >> 5;
            int il = rem / 3, d3 = rem - il * 3;
            float a = b_d2[h];
#pragma unroll
            for (int k = 0; k < 64; k++)
                a += sHd[(il * 3 + d3) * 64 + k] * W_d2[k * 32 + h];
            out[524288 + ((size_t)(b * 128 + i0 + il) * 3 + d3) * 32 + h] = a;
        }
    }
}

// ---------------- launch ----------------
extern "C" void kernel_launch(void* const* d_in, const int* in_sizes, int n_in,
                              void* d_out, int out_size) {
    const float* x = (const float*)d_in[0];
    const float* context = (const float*)d_in[1];
    const float* dis = (const float*)d_in[2];
    const float* dis_emb = (const float*)d_in[3];
    int wb = (n_in == 17) ? 4 : 6;
    const float* W_qk = (const float*)d_in[wb + 0];
    const float* W_cqk = (const float*)d_in[wb + 2];
    const float* W_cv = (const float*)d_in[wb + 3];
    const float* W_m1 = (const float*)d_in[wb + 4];
    const float* W_m2 = (const float*)d_in[wb + 5];
    const float* b_m2 = (const float*)d_in[wb + 6];
    const float* W_o = (const float*)d_in[wb + 7];
    const float* b_o = (const float*)d_in[wb + 8];
    const float* W_d1 = (const float*)d_in[wb + 9];
    const float* b_d1 = (const float*)d_in[wb + 10];
    const float* W_d2 = (const float*)d_in[wb + 11];
    const float* b_d2 = (const float*)d_in[wb + 12];
    float* out = (float*)d_out;

    proj_fused<<<dim3(128, 8, 3), 256, PROJ_SMEM_BYTES>>>(x, context, W_qk,
                                                          W_cqk, W_cv);

    cudaFuncSetAttribute(score_kernel, cudaFuncAttributeMaxDynamicSharedMemorySize,
                         K1_BYTES);
    cudaFuncSetAttribute(attend_partial, cudaFuncAttributeMaxDynamicSharedMemorySize,
                         K2_BYTES);
    cudaFuncSetAttribute(reduce_kernel, cudaFuncAttributeMaxDynamicSharedMemorySize,
                         K3_BYTES);
    score_kernel<<<dim3(16, 8, 16), 512, K1_BYTES>>>(dis_emb, W_m1, W_m2, b_m2);
    attend_partial<<<dim3(16, 16, 4), 512, K2_BYTES>>>(dis);
    reduce_kernel<<<dim3(8 * 2, 16), 512, K3_BYTES>>>(W_o, b_o, W_d1, b_d1,
                                                      W_d2, b_d2, out);
}